// round 12
// baseline (speedup 1.0000x reference)
#include <cuda_runtime.h>
#include <math.h>
#include <stdint.h>

#define NROWS 16384
#define NCOLS 1024
#define ROW_BYTES 4096
#define BLOCKS 148                    // 1 CTA per SM
#define THREADS 512
#define CHUNK_ROWS 8
#define CHUNK_BYTES (CHUNK_ROWS * ROW_BYTES)   // 32768
#define STAGES 4
#define DYN_SMEM (STAGES * CHUNK_BYTES)        // 131072
#define NBUCKETS 8

__device__ float g_colsum[NBUCKETS][NCOLS];   // zero-init at module load
__device__ float g_sqsum;
__device__ unsigned int g_count;

__device__ __forceinline__ uint32_t smem_u32(const void* p) {
    uint32_t a;
    asm("{ .reg .u64 t; cvta.to.shared.u64 t, %1; cvt.u32.u64 %0, t; }"
        : "=r"(a) : "l"(p));
    return a;
}

#define MBAR_INIT(addr, cnt) \
    asm volatile("mbarrier.init.shared.b64 [%0], %1;" :: "r"(addr), "r"(cnt) : "memory")
#define MBAR_EXPECT_TX(addr, bytes) \
    asm volatile("mbarrier.arrive.expect_tx.shared.b64 _, [%0], %1;" :: "r"(addr), "r"(bytes) : "memory")
#define MBAR_ARRIVE(addr) \
    asm volatile("mbarrier.arrive.shared.b64 _, [%0];" :: "r"(addr) : "memory")
#define MBAR_WAIT(addr, ph) do {                                                   \
    uint32_t _done;                                                                \
    asm volatile("{ .reg .pred p; "                                                \
        "mbarrier.try_wait.parity.acquire.cta.shared::cta.b64 p, [%1], %2; "       \
        "selp.b32 %0, 1, 0, p; }" : "=r"(_done) : "r"(addr), "r"(ph) : "memory");  \
    while (!_done) {                                                               \
        asm volatile("{ .reg .pred p; "                                            \
            "mbarrier.try_wait.parity.acquire.cta.shared::cta.b64 p, [%1], %2, 0x989680; " \
            "selp.b32 %0, 1, 0, p; }" : "=r"(_done) : "r"(addr), "r"(ph) : "memory"); \
    }                                                                              \
} while (0)

// 1D bulk async copy global -> shared, completion via mbarrier complete_tx.
#define BULK_G2S(dst, src, bytes, mbar) \
    asm volatile("cp.async.bulk.shared::cluster.global.mbarrier::complete_tx::bytes [%0], [%1], %2, [%3];" \
        :: "r"(dst), "l"(src), "r"(bytes), "r"(mbar) : "memory")

__device__ __forceinline__ float warp_reduce_sum(float v) {
    #pragma unroll
    for (int off = 16; off > 0; off >>= 1)
        v += __shfl_xor_sync(0xFFFFFFFFu, v, off);
    return v;
}

__global__ void __launch_bounds__(THREADS, 1)
l2_tma_kernel(const float* __restrict__ feats, float* __restrict__ out) {
    extern __shared__ char sm[];                 // STAGES x CHUNK_BYTES
    __shared__ uint64_t mbar[2 * STAGES];        // full[0..3], empty[4..7]
    __shared__ float4 s_part[256];
    __shared__ float s_warp[THREADS / 32];
    __shared__ int s_last;

    const int t = threadIdx.x;
    const int bid = blockIdx.x;
    const int sub = t >> 8;                      // 0..1
    const int cg  = t & 255;                     // float4 column group

    const uint32_t mb = smem_u32(mbar);
    if (t == 0) {
        #pragma unroll
        for (int s = 0; s < STAGES; s++) {
            MBAR_INIT(mb + 8u * s, 1);                       // full: tx-completed
            MBAR_INIT(mb + 8u * (STAGES + s), THREADS);      // empty: all consumers
        }
    }
    asm volatile("fence.proxy.async.shared::cta;" ::: "memory");
    __syncthreads();

    // Balanced contiguous stripes: rpb=110, first 104 blocks get 111.
    const int rpb  = NROWS / BLOCKS;             // 110
    const int rem  = NROWS % BLOCKS;             // 104
    const int row0 = bid * rpb + (bid < rem ? bid : rem);
    const int nrows = rpb + (bid < rem ? 1 : 0);
    const int nch = (nrows + CHUNK_ROWS - 1) / CHUNK_ROWS;
    const int total_bytes = nrows * ROW_BYTES;

    const char* src = (const char*)feats + (size_t)row0 * ROW_BYTES;
    const uint32_t sm_base = smem_u32(sm);

    float4 cs = make_float4(0.f, 0.f, 0.f, 0.f);
    float sq = 0.f;

    for (int c = 0; c < nch; c++) {
        const int s = c & (STAGES - 1);
        const int round = c >> 2;                // STAGES == 4
        if (t == 0) {
            if (c >= STAGES) MBAR_WAIT(mb + 8u * (STAGES + s), (round - 1) & 1);
            int bytes = total_bytes - c * CHUNK_BYTES;
            if (bytes > CHUNK_BYTES) bytes = CHUNK_BYTES;
            MBAR_EXPECT_TX(mb + 8u * s, (uint32_t)bytes);
            BULK_G2S(sm_base + (uint32_t)(s * CHUNK_BYTES),
                     src + (size_t)c * CHUNK_BYTES,
                     (uint32_t)bytes, mb + 8u * s);
        }
        MBAR_WAIT(mb + 8u * s, round & 1);

        int rrows = nrows - c * CHUNK_ROWS;
        if (rrows > CHUNK_ROWS) rrows = CHUNK_ROWS;
        const char* base = sm + s * CHUNK_BYTES;
        for (int r = sub; r < rrows; r += 2) {
            float4 v = *(const float4*)(base + r * ROW_BYTES + cg * 16);
            cs.x += v.x; cs.y += v.y; cs.z += v.z; cs.w += v.w;
            sq = fmaf(v.x, v.x, sq); sq = fmaf(v.y, v.y, sq);
            sq = fmaf(v.z, v.z, sq); sq = fmaf(v.w, v.w, sq);
        }
        MBAR_ARRIVE(mb + 8u * (STAGES + s));     // stage consumed
    }

    // Combine the 2 subrow partials per column group; sub==0 issues atomics.
    if (sub != 0) s_part[cg] = cs;

    float wsum = warp_reduce_sum(sq);
    int lane = t & 31, wid = t >> 5;
    if (lane == 0) s_warp[wid] = wsum;
    __syncthreads();

    if (sub == 0) {
        float4 a = s_part[cg];
        cs.x += a.x; cs.y += a.y; cs.z += a.z; cs.w += a.w;
        float* bucket = g_colsum[bid & (NBUCKETS - 1)];
        atomicAdd(&bucket[4 * cg + 0], cs.x);
        atomicAdd(&bucket[4 * cg + 1], cs.y);
        atomicAdd(&bucket[4 * cg + 2], cs.z);
        atomicAdd(&bucket[4 * cg + 3], cs.w);
    }
    if (wid == 0) {
        float v = (lane < THREADS / 32) ? s_warp[lane] : 0.f;
        v = warp_reduce_sum(v);
        if (lane == 0) atomicAdd(&g_sqsum, v);
    }

    // Last-block vote (fence makes our atomics globally visible first).
    __threadfence();
    if (t == 0) {
        unsigned int prev = atomicAdd(&g_count, 1u);
        s_last = (prev == BLOCKS - 1u) ? 1 : 0;
    }
    __syncthreads();

    if (s_last) {
        float d = 0.f;
        #pragma unroll
        for (int i = t; i < NCOLS; i += THREADS) {
            float c = 0.f;
            #pragma unroll
            for (int b = 0; b < NBUCKETS; b++) {
                c += __ldcg(&g_colsum[b][i]);
                g_colsum[b][i] = 0.f;            // reset for next graph replay
            }
            d = fmaf(c, c, d);
        }
        float wd = warp_reduce_sum(d);
        if (lane == 0) s_warp[wid] = wd;
        __syncthreads();
        if (wid == 0) {
            float v = (lane < THREADS / 32) ? s_warp[lane] : 0.f;
            v = warp_reduce_sum(v);
            if (lane == 0) {
                double sqtot = (double)__ldcg(&g_sqsum);
                double dot = (double)v;
                double pair_sum = (double)NROWS * sqtot - dot;
                double count = (double)NROWS * (NROWS - 1) / 2.0;
                out[0] = (float)exp(-pair_sum / count);
                g_sqsum = 0.f;
                g_count = 0u;
            }
        }
    }
}

extern "C" void kernel_launch(void* const* d_in, const int* in_sizes, int n_in,
                              void* d_out, int out_size) {
    const float* feats = (const float*)d_in[0];
    float* out = (float*)d_out;
    cudaFuncSetAttribute(l2_tma_kernel,
                         cudaFuncAttributeMaxDynamicSharedMemorySize, DYN_SMEM);
    l2_tma_kernel<<<BLOCKS, THREADS, DYN_SMEM>>>(feats, out);
}

// round 13
// speedup vs baseline: 1.2557x; 1.2557x over previous
#include <cuda_runtime.h>
#include <math.h>

#define NROWS 16384
#define NCOLS 1024
#define F4_PER_ROW (NCOLS / 4)        // 256
#define BLOCKS 592                    // 4 CTAs/SM x 148 SMs -> 64 warps/SM
#define THREADS 512
#define NBUCKETS 8

__device__ float g_colsum[NBUCKETS][NCOLS];   // zero-init at module load
__device__ float g_sqsum;
__device__ unsigned int g_count;

__device__ __forceinline__ float warp_reduce_sum(float v) {
    #pragma unroll
    for (int off = 16; off > 0; off >>= 1)
        v += __shfl_xor_sync(0xFFFFFFFFu, v, off);
    return v;
}

__device__ __forceinline__ void acc(const float4& v, float4& cs, float& sq) {
    cs.x += v.x; cs.y += v.y; cs.z += v.z; cs.w += v.w;
    sq = fmaf(v.x, v.x, sq); sq = fmaf(v.y, v.y, sq);
    sq = fmaf(v.z, v.z, sq); sq = fmaf(v.w, v.w, sq);
}

__global__ void __launch_bounds__(THREADS, 4)
l2_fused_kernel(const float* __restrict__ feats, float* __restrict__ out) {
    const int t = threadIdx.x;
    const int bid = blockIdx.x;
    const int sub = t >> 8;            // 0..1: which row parity
    const int cg  = t & 255;           // float4 column group
    const float4* __restrict__ f4 = reinterpret_cast<const float4*>(feats);

    // Balanced contiguous stripes: rpb=27, first 400 blocks get 28.
    const int rpb  = NROWS / BLOCKS;           // 27
    const int rem  = NROWS % BLOCKS;           // 400
    const int row0 = bid * rpb + (bid < rem ? bid : rem);
    const int nrows = rpb + (bid < rem ? 1 : 0);

    float4 cs0 = make_float4(0.f, 0.f, 0.f, 0.f);
    float4 cs1 = make_float4(0.f, 0.f, 0.f, 0.f);
    float sq0 = 0.f, sq1 = 0.f;

    // Thread covers rows row0+sub, +2, +4, ... ; 4 independent LDG.128.CG
    // issued back-to-back per iteration (MLP 4) x 64 warps/SM.
    const float4* p = f4 + (size_t)(row0 + sub) * F4_PER_ROW + cg;
    int r = sub;
    for (; r + 6 < nrows; r += 8) {
        float4 v0 = __ldcg(p + 0 * 2 * F4_PER_ROW);
        float4 v1 = __ldcg(p + 1 * 2 * F4_PER_ROW);
        float4 v2 = __ldcg(p + 2 * 2 * F4_PER_ROW);
        float4 v3 = __ldcg(p + 3 * 2 * F4_PER_ROW);
        p += 8 * F4_PER_ROW;
        acc(v0, cs0, sq0); acc(v1, cs1, sq1);
        acc(v2, cs0, sq0); acc(v3, cs1, sq1);
    }
    for (; r < nrows; r += 2) {
        float4 v = __ldcg(p);
        p += 2 * F4_PER_ROW;
        acc(v, cs0, sq0);
    }
    cs0.x += cs1.x; cs0.y += cs1.y; cs0.z += cs1.z; cs0.w += cs1.w;
    float sq = sq0 + sq1;

    // Combine the 2 subrow partials per column group in SMEM; only sub==0
    // (warps 0-7) issues the 1024 global atomics per block.
    __shared__ float4 s_part[256];             // 4 KB
    __shared__ float s_warp[THREADS / 32];
    __shared__ int s_last;

    if (sub != 0) s_part[cg] = cs0;

    float wsum = warp_reduce_sum(sq);
    int lane = t & 31, wid = t >> 5;
    if (lane == 0) s_warp[wid] = wsum;
    __syncthreads();

    if (sub == 0) {
        float4 a = s_part[cg];
        cs0.x += a.x; cs0.y += a.y; cs0.z += a.z; cs0.w += a.w;
        float* bucket = g_colsum[bid & (NBUCKETS - 1)];
        atomicAdd(&bucket[4 * cg + 0], cs0.x);
        atomicAdd(&bucket[4 * cg + 1], cs0.y);
        atomicAdd(&bucket[4 * cg + 2], cs0.z);
        atomicAdd(&bucket[4 * cg + 3], cs0.w);
    }
    if (wid == 0) {
        float v = (lane < THREADS / 32) ? s_warp[lane] : 0.f;
        v = warp_reduce_sum(v);
        if (lane == 0) atomicAdd(&g_sqsum, v);
    }

    // Last-block vote (fence makes our atomics globally visible first).
    __threadfence();
    if (t == 0) {
        unsigned int prev = atomicAdd(&g_count, 1u);
        s_last = (prev == BLOCKS - 1u) ? 1 : 0;
    }
    __syncthreads();

    if (s_last) {
        // Fold 8 buckets, square, reset state for the next graph replay.
        float d = 0.f;
        #pragma unroll
        for (int i = t; i < NCOLS; i += THREADS) {
            float c = 0.f;
            #pragma unroll
            for (int b = 0; b < NBUCKETS; b++) {
                c += __ldcg(&g_colsum[b][i]);
                g_colsum[b][i] = 0.f;
            }
            d = fmaf(c, c, d);
        }
        float wd = warp_reduce_sum(d);
        if (lane == 0) s_warp[wid] = wd;
        __syncthreads();
        if (wid == 0) {
            float v = (lane < THREADS / 32) ? s_warp[lane] : 0.f;
            v = warp_reduce_sum(v);
            if (lane == 0) {
                double sqtot = (double)__ldcg(&g_sqsum);
                double dot = (double)v;
                double pair_sum = (double)NROWS * sqtot - dot;
                double count = (double)NROWS * (NROWS - 1) / 2.0;
                out[0] = (float)exp(-pair_sum / count);
                g_sqsum = 0.f;
                g_count = 0u;
            }
        }
    }
}

extern "C" void kernel_launch(void* const* d_in, const int* in_sizes, int n_in,
                              void* d_out, int out_size) {
    const float* feats = (const float*)d_in[0];
    float* out = (float*)d_out;
    l2_fused_kernel<<<BLOCKS, THREADS>>>(feats, out);
}

// round 14
// speedup vs baseline: 1.2581x; 1.0019x over previous
#include <cuda_runtime.h>
#include <math.h>
#include <stdint.h>

#define NROWS 16384
#define NCOLS 1024
#define ROW_BYTES 4096
#define BLOCKS 296                    // 2 CTAs/SM x 148 SMs -> 64 warps/SM
#define THREADS 1024
#define CHUNK_ROWS 4                  // 1024 threads x 16B = 16KB = 4 rows
#define STAGE_BYTES (CHUNK_ROWS * ROW_BYTES)   // 16384
#define STAGES 4                      // 64KB dynamic smem, MLP ~3-4 per thread, reg-free
#define DYN_SMEM (STAGES * STAGE_BYTES)
#define NBUCKETS 8

__device__ float g_colsum[NBUCKETS][NCOLS];   // zero-init at module load
__device__ float g_sqsum;
__device__ unsigned int g_count;

__device__ __forceinline__ uint32_t smem_u32(const void* p) {
    uint32_t a;
    asm("{ .reg .u64 t; cvta.to.shared.u64 t, %1; cvt.u32.u64 %0, t; }"
        : "=r"(a) : "l"(p));
    return a;
}

#define CP_ASYNC16(dst, src) \
    asm volatile("cp.async.cg.shared.global [%0], [%1], 16;" :: "r"(dst), "l"(src) : "memory")
#define CP_COMMIT() asm volatile("cp.async.commit_group;" ::: "memory")
#define CP_WAIT(n)  asm volatile("cp.async.wait_group %0;" :: "n"(n) : "memory")

__device__ __forceinline__ float warp_reduce_sum(float v) {
    #pragma unroll
    for (int off = 16; off > 0; off >>= 1)
        v += __shfl_xor_sync(0xFFFFFFFFu, v, off);
    return v;
}

__device__ __forceinline__ void acc(const float4& v, float4& cs, float& sq) {
    cs.x += v.x; cs.y += v.y; cs.z += v.z; cs.w += v.w;
    sq = fmaf(v.x, v.x, sq); sq = fmaf(v.y, v.y, sq);
    sq = fmaf(v.z, v.z, sq); sq = fmaf(v.w, v.w, sq);
}

__global__ void __launch_bounds__(THREADS, 2)
l2_cpasync_kernel(const float* __restrict__ feats, float* __restrict__ out) {
    extern __shared__ char dyn[];              // STAGES x STAGE_BYTES
    __shared__ float4 s_part[3][256];          // 12 KB: sub 1..3 partials
    __shared__ float s_warp[THREADS / 32];
    __shared__ int s_last;

    const int t = threadIdx.x;
    const int bid = blockIdx.x;
    const int sub = t >> 8;                    // 0..3: row within chunk
    const int cg  = t & 255;                   // float4 column group

    // Balanced contiguous stripes: rpb=55, first 104 blocks get 56.
    const int rpb  = NROWS / BLOCKS;           // 55
    const int rem  = NROWS % BLOCKS;           // 104
    const int row0 = bid * rpb + (bid < rem ? bid : rem);
    const int nrows = rpb + (bid < rem ? 1 : 0);
    const int nch = (nrows + CHUNK_ROWS - 1) / CHUNK_ROWS;

    const uint32_t my_dst = smem_u32(dyn) + (uint32_t)t * 16u;
    const char* my_src = (const char*)feats
                       + ((size_t)row0 + (size_t)sub) * ROW_BYTES
                       + (size_t)cg * 16u;
    const char* my_slot = dyn + (size_t)t * 16u;

    float4 cs = make_float4(0.f, 0.f, 0.f, 0.f);
    float sq = 0.f;

    // Per-thread cp.async pipeline: thread t copies and consumes ONLY its own
    // 16 bytes per chunk -> commit/wait_group gives all the ordering we need;
    // no __syncthreads in the main loop. MLP = STAGES-1 in-flight 16B copies
    // per thread x 64 warps/SM, at zero register cost.
    for (int c = 0; c < nch; c++) {
        int row = c * CHUNK_ROWS + sub;
        if (row < nrows)
            CP_ASYNC16(my_dst + (uint32_t)((c & (STAGES - 1)) * STAGE_BYTES),
                       my_src + (size_t)c * STAGE_BYTES);
        CP_COMMIT();
        if (c >= STAGES - 1) {
            CP_WAIT(STAGES - 1);
            int cc = c - (STAGES - 1);
            // crow = cc*4+sub < nrows always here (cc <= nch-STAGES)
            float4 v = *(const float4*)(my_slot + (cc & (STAGES - 1)) * STAGE_BYTES);
            acc(v, cs, sq);
        }
    }
    CP_WAIT(0);
    {
        int cc0 = nch - (STAGES - 1);
        if (cc0 < 0) cc0 = 0;
        for (int cc = cc0; cc < nch; cc++) {
            int crow = cc * CHUNK_ROWS + sub;
            if (crow < nrows) {
                float4 v = *(const float4*)(my_slot + (cc & (STAGES - 1)) * STAGE_BYTES);
                acc(v, cs, sq);
            }
        }
    }

    // Combine 4 subrow partials per column group in SMEM; only sub==0
    // (warps 0-7) issues the 1024 global atomics per block.
    if (sub != 0) s_part[sub - 1][cg] = cs;

    float wsum = warp_reduce_sum(sq);
    int lane = t & 31, wid = t >> 5;
    if (lane == 0) s_warp[wid] = wsum;
    __syncthreads();

    if (sub == 0) {
        float4 a = s_part[0][cg], b = s_part[1][cg], c4 = s_part[2][cg];
        cs.x += a.x + b.x + c4.x;
        cs.y += a.y + b.y + c4.y;
        cs.z += a.z + b.z + c4.z;
        cs.w += a.w + b.w + c4.w;
        float* bucket = g_colsum[bid & (NBUCKETS - 1)];
        atomicAdd(&bucket[4 * cg + 0], cs.x);
        atomicAdd(&bucket[4 * cg + 1], cs.y);
        atomicAdd(&bucket[4 * cg + 2], cs.z);
        atomicAdd(&bucket[4 * cg + 3], cs.w);
    }
    if (wid == 0) {
        float v = (lane < THREADS / 32) ? s_warp[lane] : 0.f;
        v = warp_reduce_sum(v);
        if (lane == 0) atomicAdd(&g_sqsum, v);
    }

    // Last-block vote (fence makes our atomics globally visible first).
    __threadfence();
    if (t == 0) {
        unsigned int prev = atomicAdd(&g_count, 1u);
        s_last = (prev == BLOCKS - 1u) ? 1 : 0;
    }
    __syncthreads();

    if (s_last) {
        // Fold 8 buckets, square, reset state for the next graph replay.
        float c = 0.f;
        #pragma unroll
        for (int b = 0; b < NBUCKETS; b++) {
            c += __ldcg(&g_colsum[b][t]);
            g_colsum[b][t] = 0.f;
        }
        float d = c * c;
        float wd = warp_reduce_sum(d);
        if (lane == 0) s_warp[wid] = wd;
        __syncthreads();
        if (wid == 0) {
            float v = (lane < THREADS / 32) ? s_warp[lane] : 0.f;
            v = warp_reduce_sum(v);
            if (lane == 0) {
                double sqtot = (double)__ldcg(&g_sqsum);
                double dot = (double)v;
                double pair_sum = (double)NROWS * sqtot - dot;
                double count = (double)NROWS * (NROWS - 1) / 2.0;
                out[0] = (float)exp(-pair_sum / count);
                g_sqsum = 0.f;
                g_count = 0u;
            }
        }
    }
}

extern "C" void kernel_launch(void* const* d_in, const int* in_sizes, int n_in,
                              void* d_out, int out_size) {
    const float* feats = (const float*)d_in[0];
    float* out = (float*)d_out;
    cudaFuncSetAttribute(l2_cpasync_kernel,
                         cudaFuncAttributeMaxDynamicSharedMemorySize, DYN_SMEM);
    l2_cpasync_kernel<<<BLOCKS, THREADS, DYN_SMEM>>>(feats, out);
}